// round 10
// baseline (speedup 1.0000x reference)
#include <cuda_runtime.h>

// GraphConv: out = (feat + scatter_sum(feat[src]*norm_l[src] -> dst)) * norm_r
// norm_l = rsqrt(max(out_deg,1)+1), norm_r = rsqrt(max(in_deg,1)+1)
// N=100000 nodes, D=64 f32 features, E=1.25M edges (int32 indices).
//
// Strategy: counting-sort edges by dst into a CSR edge list, then one warp
// per dst node accumulates its neighbor sum in registers (no feature
// atomics), fusing the self-connection + right-normalization into the
// single output store.

#define N_MAX 100000
#define E_MAX 1250000
#define D 64
#define SCAN_THREADS 1024

__device__ int   g_outdeg[N_MAX];
__device__ int   g_indeg[N_MAX];
__device__ int   g_cursor[N_MAX];
__device__ int   g_row_start[N_MAX + 1];
__device__ float g_norml[N_MAX];
__device__ float g_normr[N_MAX];
__device__ int   g_edge_src[E_MAX];

// ---------------------------------------------------------------------------
// 1) zero degree + cursor scratch (out is fully overwritten by k_aggregate)
// ---------------------------------------------------------------------------
__global__ void k_zero(int n) {
    int stride = gridDim.x * blockDim.x;
    for (int j = blockIdx.x * blockDim.x + threadIdx.x; j < n; j += stride) {
        g_outdeg[j] = 0;
        g_indeg[j]  = 0;
        g_cursor[j] = 0;
    }
}

// ---------------------------------------------------------------------------
// 2) degree counting (int REDG)
// ---------------------------------------------------------------------------
__global__ void k_degree(const int* __restrict__ src,
                         const int* __restrict__ dst, int E) {
    int i = blockIdx.x * blockDim.x + threadIdx.x;
    if (i < E) {
        atomicAdd(&g_outdeg[src[i]], 1);
        atomicAdd(&g_indeg[dst[i]], 1);
    }
}

// ---------------------------------------------------------------------------
// 3) normalization factors
// ---------------------------------------------------------------------------
__global__ void k_norm(int n) {
    int i = blockIdx.x * blockDim.x + threadIdx.x;
    if (i < n) {
        g_norml[i] = rsqrtf(fmaxf((float)g_outdeg[i], 1.0f) + 1.0f);
        g_normr[i] = rsqrtf(fmaxf((float)g_indeg[i], 1.0f) + 1.0f);
    }
}

// ---------------------------------------------------------------------------
// 4) exclusive prefix scan of in-degrees -> CSR row offsets.
//    Single block of 1024 threads; each thread owns a contiguous chunk.
// ---------------------------------------------------------------------------
__global__ void k_scan(int n, int E) {
    __shared__ int sh[SCAN_THREADS];
    int t = threadIdx.x;
    int chunk = (n + SCAN_THREADS - 1) / SCAN_THREADS;
    int beg = t * chunk;
    int end = min(beg + chunk, n);

    int sum = 0;
    for (int i = beg; i < end; i++) sum += g_indeg[i];
    sh[t] = sum;
    __syncthreads();

    // Hillis-Steele inclusive scan over the 1024 per-thread sums
    for (int off = 1; off < SCAN_THREADS; off <<= 1) {
        int tmp = (t >= off) ? sh[t - off] : 0;
        __syncthreads();
        sh[t] += tmp;
        __syncthreads();
    }

    int run = sh[t] - sum;   // exclusive prefix for this chunk
    for (int i = beg; i < end; i++) {
        g_row_start[i] = run;
        run += g_indeg[i];
    }
    if (t == SCAN_THREADS - 1) g_row_start[n] = E;
}

// ---------------------------------------------------------------------------
// 5) fill CSR edge list: bucket src ids by dst
// ---------------------------------------------------------------------------
__global__ void k_fill(const int* __restrict__ src,
                       const int* __restrict__ dst, int E) {
    int i = blockIdx.x * blockDim.x + threadIdx.x;
    if (i < E) {
        int d = dst[i];
        int pos = g_row_start[d] + atomicAdd(&g_cursor[d], 1);
        g_edge_src[pos] = src[i];
    }
}

// ---------------------------------------------------------------------------
// 6) aggregate: one warp per dst node. Lane l owns float2 [2l, 2l+1].
//    For each incoming edge: broadcast src id, coalesced 256B float2 gather
//    of feat[src] (L2-resident), register accumulate. Single output store
//    fuses self-connection + right-normalization. No atomics.
// ---------------------------------------------------------------------------
__global__ void k_aggregate(const float* __restrict__ feat,
                            float* __restrict__ out, int n) {
    int node = (blockIdx.x * blockDim.x + threadIdx.x) >> 5;
    int lane = threadIdx.x & 31;
    if (node >= n) return;

    int beg = g_row_start[node];
    int end = g_row_start[node + 1];

    float ax = 0.f, ay = 0.f;
    int j = beg;
    // 4-way unroll for memory-level parallelism on the gathers
    for (; j + 4 <= end; j += 4) {
        int s0 = g_edge_src[j + 0];
        int s1 = g_edge_src[j + 1];
        int s2 = g_edge_src[j + 2];
        int s3 = g_edge_src[j + 3];
        float n0 = g_norml[s0], n1 = g_norml[s1];
        float n2 = g_norml[s2], n3 = g_norml[s3];
        float2 v0 = *reinterpret_cast<const float2*>(feat + ((long)s0 << 6) + (lane << 1));
        float2 v1 = *reinterpret_cast<const float2*>(feat + ((long)s1 << 6) + (lane << 1));
        float2 v2 = *reinterpret_cast<const float2*>(feat + ((long)s2 << 6) + (lane << 1));
        float2 v3 = *reinterpret_cast<const float2*>(feat + ((long)s3 << 6) + (lane << 1));
        ax += v0.x * n0 + v1.x * n1 + v2.x * n2 + v3.x * n3;
        ay += v0.y * n0 + v1.y * n1 + v2.y * n2 + v3.y * n3;
    }
    for (; j < end; j++) {
        int s = g_edge_src[j];
        float nl = g_norml[s];
        float2 v = *reinterpret_cast<const float2*>(feat + ((long)s << 6) + (lane << 1));
        ax += v.x * nl;
        ay += v.y * nl;
    }

    float nr = g_normr[node];
    float2 f = *reinterpret_cast<const float2*>(feat + ((long)node << 6) + (lane << 1));
    float2 r;
    r.x = (f.x + ax) * nr;
    r.y = (f.y + ay) * nr;
    *reinterpret_cast<float2*>(out + ((long)node << 6) + (lane << 1)) = r;
}

extern "C" void kernel_launch(void* const* d_in, const int* in_sizes, int n_in,
                              void* d_out, int out_size) {
    const float* feat = (const float*)d_in[0];
    const int*   src  = (const int*)d_in[1];
    const int*   dst  = (const int*)d_in[2];
    float*       out  = (float*)d_out;

    int n = in_sizes[0] / D;      // 100000
    int E = in_sizes[1];          // 1250000

    k_zero<<<256, 256>>>(n);
    k_degree<<<(E + 255) / 256, 256>>>(src, dst, E);
    k_norm<<<(n + 255) / 256, 256>>>(n);
    k_scan<<<1, SCAN_THREADS>>>(n, E);
    k_fill<<<(E + 255) / 256, 256>>>(src, dst, E);
    {
        long long threads = (long long)n * 32;
        int blocks = (int)((threads + 255) / 256);
        k_aggregate<<<blocks, 256>>>(feat, out, n);
    }
}

// round 11
// speedup vs baseline: 2.4555x; 2.4555x over previous
#include <cuda_runtime.h>

// GraphConv: out = (feat + scatter_sum(feat[src]*norm_l[src] -> dst)) * norm_r
// norm_l = rsqrt(max(out_deg,1)+1), norm_r = rsqrt(max(in_deg,1)+1)
// N=100000 nodes, D=64 f32 features, E=1.25M edges (int32 indices).
//
// CSR-by-dst counting sort + warp-per-node register aggregation (no feature
// atomics). The R10 bottleneck (single-block serial scan, 106us) is replaced
// by a 3-pass device-wide scan (~5us).

#define N_MAX 100000
#define E_MAX 1250000
#define D 64
#define CHUNK 1024           // elements scanned per block in pass 1
#define BTHREADS 256         // threads per scan block (4 elems/thread)
#define MAX_BLOCKS 128       // ceil(N_MAX/CHUNK) = 98 <= 128

__device__ int   g_outdeg[N_MAX];
__device__ int   g_indeg[N_MAX];
__device__ int   g_cursor[N_MAX];
__device__ int   g_row_start[N_MAX + 1];
__device__ int   g_bsum[MAX_BLOCKS];
__device__ float g_norml[N_MAX];
__device__ float g_normr[N_MAX];
__device__ int   g_edge_src[E_MAX];

// ---------------------------------------------------------------------------
// 1) zero degree scratch
// ---------------------------------------------------------------------------
__global__ void k_zero(int n) {
    int stride = gridDim.x * blockDim.x;
    for (int j = blockIdx.x * blockDim.x + threadIdx.x; j < n; j += stride) {
        g_outdeg[j] = 0;
        g_indeg[j]  = 0;
    }
}

// ---------------------------------------------------------------------------
// 2) degree counting (int REDG)
// ---------------------------------------------------------------------------
__global__ void k_degree(const int* __restrict__ src,
                         const int* __restrict__ dst, int E) {
    int i = blockIdx.x * blockDim.x + threadIdx.x;
    if (i < E) {
        atomicAdd(&g_outdeg[src[i]], 1);
        atomicAdd(&g_indeg[dst[i]], 1);
    }
}

// ---------------------------------------------------------------------------
// 3) normalization factors
// ---------------------------------------------------------------------------
__global__ void k_norm(int n) {
    int i = blockIdx.x * blockDim.x + threadIdx.x;
    if (i < n) {
        g_norml[i] = rsqrtf(fmaxf((float)g_outdeg[i], 1.0f) + 1.0f);
        g_normr[i] = rsqrtf(fmaxf((float)g_indeg[i], 1.0f) + 1.0f);
    }
}

// ---------------------------------------------------------------------------
// 4a) scan pass 1: per-block local exclusive scan of indeg (1024/block),
//     block total -> g_bsum[b]
// ---------------------------------------------------------------------------
__global__ void k_scan1(int n) {
    __shared__ int warp_sums[BTHREADS / 32];
    int b = blockIdx.x;
    int t = threadIdx.x;
    int i0 = b * CHUNK + t * 4;

    int v0 = (i0 + 0 < n) ? g_indeg[i0 + 0] : 0;
    int v1 = (i0 + 1 < n) ? g_indeg[i0 + 1] : 0;
    int v2 = (i0 + 2 < n) ? g_indeg[i0 + 2] : 0;
    int v3 = (i0 + 3 < n) ? g_indeg[i0 + 3] : 0;
    int tsum = v0 + v1 + v2 + v3;

    int lane = t & 31, wid = t >> 5;
    int x = tsum;                                   // warp inclusive scan
    #pragma unroll
    for (int off = 1; off < 32; off <<= 1) {
        int y = __shfl_up_sync(0xffffffffu, x, off);
        if (lane >= off) x += y;
    }
    if (lane == 31) warp_sums[wid] = x;
    __syncthreads();
    if (wid == 0) {
        int w = (lane < BTHREADS / 32) ? warp_sums[lane] : 0;
        #pragma unroll
        for (int off = 1; off < BTHREADS / 32; off <<= 1) {
            int y = __shfl_up_sync(0xffffffffu, w, off);
            if (lane >= off) w += y;
        }
        if (lane < BTHREADS / 32) warp_sums[lane] = w;
    }
    __syncthreads();

    int excl = x - tsum + (wid > 0 ? warp_sums[wid - 1] : 0);
    if (i0 + 0 < n) g_row_start[i0 + 0] = excl;
    if (i0 + 1 < n) g_row_start[i0 + 1] = excl + v0;
    if (i0 + 2 < n) g_row_start[i0 + 2] = excl + v0 + v1;
    if (i0 + 3 < n) g_row_start[i0 + 3] = excl + v0 + v1 + v2;
    if (t == BTHREADS - 1) g_bsum[b] = excl + tsum;  // block total
}

// ---------------------------------------------------------------------------
// 4b) scan pass 2: exclusive scan of the (<=128) block sums, one block
// ---------------------------------------------------------------------------
__global__ void k_scan2(int nb) {
    __shared__ int warp_sums[4];
    int t = threadIdx.x;            // 128 threads
    int lane = t & 31, wid = t >> 5;
    int v = (t < nb) ? g_bsum[t] : 0;
    int x = v;
    #pragma unroll
    for (int off = 1; off < 32; off <<= 1) {
        int y = __shfl_up_sync(0xffffffffu, x, off);
        if (lane >= off) x += y;
    }
    if (lane == 31) warp_sums[wid] = x;
    __syncthreads();
    if (wid == 0 && lane < 4) {
        int w = warp_sums[lane];
        #pragma unroll
        for (int off = 1; off < 4; off <<= 1) {
            int y = __shfl_up_sync(0x0000000fu, w, off);
            if (lane >= off) w += y;
        }
        warp_sums[lane] = w;
    }
    __syncthreads();
    int incl = x + (wid > 0 ? warp_sums[wid - 1] : 0);
    if (t < nb) g_bsum[t] = incl - v;   // exclusive
}

// ---------------------------------------------------------------------------
// 4c) scan pass 3: add block offsets; seed cursors with row starts
// ---------------------------------------------------------------------------
__global__ void k_scan3(int n, int E) {
    int i = blockIdx.x * blockDim.x + threadIdx.x;
    if (i < n) {
        int rs = g_row_start[i] + g_bsum[i >> 10];   // CHUNK = 1024
        g_row_start[i] = rs;
        g_cursor[i] = rs;
    }
    if (i == 0) g_row_start[n] = E;
}

// ---------------------------------------------------------------------------
// 5) fill CSR edge list: bucket src ids by dst (cursor pre-seeded)
// ---------------------------------------------------------------------------
__global__ void k_fill(const int* __restrict__ src,
                       const int* __restrict__ dst, int E) {
    int i = blockIdx.x * blockDim.x + threadIdx.x;
    if (i < E) {
        int pos = atomicAdd(&g_cursor[dst[i]], 1);
        g_edge_src[pos] = src[i];
    }
}

// ---------------------------------------------------------------------------
// 6) aggregate: one warp per dst node. Lane l owns float2 [2l, 2l+1].
//    Broadcast src id, coalesced 256B float2 gather of feat[src]
//    (L2-resident), register accumulate; single fused output store.
// ---------------------------------------------------------------------------
__global__ void k_aggregate(const float* __restrict__ feat,
                            float* __restrict__ out, int n) {
    int node = (blockIdx.x * blockDim.x + threadIdx.x) >> 5;
    int lane = threadIdx.x & 31;
    if (node >= n) return;

    int beg = g_row_start[node];
    int end = g_row_start[node + 1];

    float ax = 0.f, ay = 0.f;
    int j = beg;
    for (; j + 4 <= end; j += 4) {
        int s0 = g_edge_src[j + 0];
        int s1 = g_edge_src[j + 1];
        int s2 = g_edge_src[j + 2];
        int s3 = g_edge_src[j + 3];
        float n0 = g_norml[s0], n1 = g_norml[s1];
        float n2 = g_norml[s2], n3 = g_norml[s3];
        float2 v0 = *reinterpret_cast<const float2*>(feat + ((long)s0 << 6) + (lane << 1));
        float2 v1 = *reinterpret_cast<const float2*>(feat + ((long)s1 << 6) + (lane << 1));
        float2 v2 = *reinterpret_cast<const float2*>(feat + ((long)s2 << 6) + (lane << 1));
        float2 v3 = *reinterpret_cast<const float2*>(feat + ((long)s3 << 6) + (lane << 1));
        ax += v0.x * n0 + v1.x * n1 + v2.x * n2 + v3.x * n3;
        ay += v0.y * n0 + v1.y * n1 + v2.y * n2 + v3.y * n3;
    }
    for (; j < end; j++) {
        int s = g_edge_src[j];
        float nl = g_norml[s];
        float2 v = *reinterpret_cast<const float2*>(feat + ((long)s << 6) + (lane << 1));
        ax += v.x * nl;
        ay += v.y * nl;
    }

    float nr = g_normr[node];
    float2 f = *reinterpret_cast<const float2*>(feat + ((long)node << 6) + (lane << 1));
    float2 r;
    r.x = (f.x + ax) * nr;
    r.y = (f.y + ay) * nr;
    *reinterpret_cast<float2*>(out + ((long)node << 6) + (lane << 1)) = r;
}

extern "C" void kernel_launch(void* const* d_in, const int* in_sizes, int n_in,
                              void* d_out, int out_size) {
    const float* feat = (const float*)d_in[0];
    const int*   src  = (const int*)d_in[1];
    const int*   dst  = (const int*)d_in[2];
    float*       out  = (float*)d_out;

    int n = in_sizes[0] / D;      // 100000
    int E = in_sizes[1];          // 1250000
    int nb = (n + CHUNK - 1) / CHUNK;   // 98 scan blocks

    k_zero<<<256, 256>>>(n);
    k_degree<<<(E + 255) / 256, 256>>>(src, dst, E);
    k_norm<<<(n + 255) / 256, 256>>>(n);
    k_scan1<<<nb, BTHREADS>>>(n);
    k_scan2<<<1, 128>>>(nb);
    k_scan3<<<(n + 255) / 256, 256>>>(n, E);
    k_fill<<<(E + 255) / 256, 256>>>(src, dst, E);
    {
        long long threads = (long long)n * 32;
        int blocks = (int)((threads + 255) / 256);
        k_aggregate<<<blocks, 256>>>(feat, out, n);
    }
}